// round 17
// baseline (speedup 1.0000x reference)
#include <cuda_runtime.h>

#define B_ 64
#define S_ 2048
#define I_ 128
#define H_ 512
#define O_ 128

// ---------------- scratch (device globals: no allocations allowed) ----------
__device__ float g_xin[(size_t)B_ * S_ * H_];   // input projection (B,S,H)
__device__ float g_hs [(size_t)B_ * S_ * H_];   // hidden states   (B,S,H)
__device__ float g_h[2][B_ * H_];               // double-buffered h
__device__ unsigned g_bar[16][32];              // 128B-padded per-group barrier

// ---------------- helpers ----------------------------------------------------
__device__ __forceinline__ unsigned long long ffma2(unsigned long long a,
                                                    unsigned long long b,
                                                    unsigned long long c) {
    unsigned long long d;
    asm("fma.rn.f32x2 %0, %1, %2, %3;" : "=l"(d) : "l"(a), "l"(b), "l"(c));
    return d;
}
__device__ __forceinline__ unsigned long long pack2(float x, float y) {
    unsigned long long p;
    asm("mov.b64 %0, {%1, %2};" : "=l"(p) : "f"(x), "f"(y));
    return p;
}
__device__ __forceinline__ float2 unpack2(unsigned long long p) {
    float2 r;
    asm("mov.b64 {%0, %1}, %2;" : "=f"(r.x), "=f"(r.y) : "l"(p));
    return r;
}
__device__ __forceinline__ float tanh_approx(float x) {
    float r;
    asm("tanh.approx.f32 %0, %1;" : "=f"(r) : "f"(x));
    return r;
}
// row-dependent column swizzle (multiple of 4 -> float4-safe, bijective/row)
__device__ __forceinline__ int swz(int row) { return ((row >> 2) & 7) * 4; }

// ---------------- init: copy h0, reset barriers ------------------------------
__global__ void init_kernel(const float* __restrict__ h0) {
    int i = blockIdx.x * blockDim.x + threadIdx.x;
    if (i < B_ * H_) g_h[0][i] = h0[i];
    if (i < 16 * 32) ((unsigned*)g_bar)[i] = 0;
}

// ---------------- dummy: shifts ncu capture alignment so scan = launch #3 ----
__global__ void dummy_kernel() {}

// ---------------- tiled fp32 GEMM:  C[M,N] = A[M,K] @ B[N,K]^T + bias --------
// 128x128 block tile, 256 threads, 8x8 per-thread tile, f32x2 FMA.
// Conflict-free staging (swizzle, R16) + conflict-free B reads (R15).
// Software pipeline: next k-tile's 8 float4 LDGs issued BEFORE the compute
// loop so DRAM/L2 latency overlaps the ~4000-cyc FFMA2 block.
template <int N, int K, bool SRC_HS, bool DST_XIN>
__global__ __launch_bounds__(256) void gemm_kernel(const float* __restrict__ Ap,
                                                   const float* __restrict__ Bm,
                                                   const float* __restrict__ bias,
                                                   float* __restrict__ Cp) {
    __shared__ __align__(16) float Ast[32][132];
    __shared__ __align__(16) float Bst[32][132];
    const float* A = SRC_HS ? g_hs : Ap;
    float* C = DST_XIN ? g_xin : Cp;

    const int tid = threadIdx.x;
    const int bm = blockIdx.x, bn = blockIdx.y;
    const float* Ab = A + (size_t)bm * 128 * K;
    const float* Bb = Bm + (size_t)bn * 128 * K;

    const int tx = tid & 15, ty = tid >> 4;

    // per-u staging indices (m, kq) are tid-invariant across tiles
    int ms[4], kqs[4];
#pragma unroll
    for (int u = 0; u < 4; u++) {
        int idx4 = tid + u * 256;
        ms[u] = idx4 >> 3;
        kqs[u] = (idx4 & 7) * 4;
    }

    unsigned long long acc2[4][8];
#pragma unroll
    for (int i = 0; i < 4; i++)
#pragma unroll
        for (int j = 0; j < 8; j++) acc2[i][j] = 0ull;

    // ---- prologue: load + stage tile 0
    float4 pa[4], pb[4];
#pragma unroll
    for (int u = 0; u < 4; u++) {
        pa[u] = *(const float4*)&Ab[(size_t)ms[u] * K + kqs[u]];
        pb[u] = *(const float4*)&Bb[(size_t)ms[u] * K + kqs[u]];
    }
#pragma unroll
    for (int u = 0; u < 4; u++) {
        int m = ms[u], kq = kqs[u];
        Ast[kq + 0][m ^ swz(kq + 0)] = pa[u].x;
        Ast[kq + 1][m ^ swz(kq + 1)] = pa[u].y;
        Ast[kq + 2][m ^ swz(kq + 2)] = pa[u].z;
        Ast[kq + 3][m ^ swz(kq + 3)] = pa[u].w;
        Bst[kq + 0][m ^ swz(kq + 0)] = pb[u].x;
        Bst[kq + 1][m ^ swz(kq + 1)] = pb[u].y;
        Bst[kq + 2][m ^ swz(kq + 2)] = pb[u].z;
        Bst[kq + 3][m ^ swz(kq + 3)] = pb[u].w;
    }
    __syncthreads();

    for (int k0 = 0; k0 < K; k0 += 32) {
        const bool more = (k0 + 32 < K);
        // ---- prefetch next tile into registers (latency hidden by compute)
        if (more) {
#pragma unroll
            for (int u = 0; u < 4; u++) {
                pa[u] = *(const float4*)&Ab[(size_t)ms[u] * K + k0 + 32 + kqs[u]];
                pb[u] = *(const float4*)&Bb[(size_t)ms[u] * K + k0 + 32 + kqs[u]];
            }
        }
        // ---- compute current tile from smem
#pragma unroll
        for (int kc = 0; kc < 32; kc++) {
            const int s = swz(kc);
            float4 a0 = *(const float4*)&Ast[kc][(ty * 8) ^ s];
            float4 a1 = *(const float4*)&Ast[kc][(ty * 8 + 4) ^ s];
            float4 b0 = *(const float4*)&Bst[kc][(tx * 4) ^ s];
            float4 b1 = *(const float4*)&Bst[kc][(64 + tx * 4) ^ s];
            unsigned long long A2[4] = {pack2(a0.x, a0.y), pack2(a0.z, a0.w),
                                        pack2(a1.x, a1.y), pack2(a1.z, a1.w)};
            float bb[8] = {b0.x, b0.y, b0.z, b0.w, b1.x, b1.y, b1.z, b1.w};
#pragma unroll
            for (int j = 0; j < 8; j++) {
                unsigned long long B2 = pack2(bb[j], bb[j]);
#pragma unroll
                for (int i = 0; i < 4; i++) acc2[i][j] = ffma2(A2[i], B2, acc2[i][j]);
            }
        }
        if (more) {
            __syncthreads();   // all reads of current tile done
#pragma unroll
            for (int u = 0; u < 4; u++) {
                int m = ms[u], kq = kqs[u];
                Ast[kq + 0][m ^ swz(kq + 0)] = pa[u].x;
                Ast[kq + 1][m ^ swz(kq + 1)] = pa[u].y;
                Ast[kq + 2][m ^ swz(kq + 2)] = pa[u].z;
                Ast[kq + 3][m ^ swz(kq + 3)] = pa[u].w;
                Bst[kq + 0][m ^ swz(kq + 0)] = pb[u].x;
                Bst[kq + 1][m ^ swz(kq + 1)] = pb[u].y;
                Bst[kq + 2][m ^ swz(kq + 2)] = pb[u].z;
                Bst[kq + 3][m ^ swz(kq + 3)] = pb[u].w;
            }
            __syncthreads();
        }
    }
#pragma unroll
    for (int i = 0; i < 4; i++) {
        size_t m0 = (size_t)bm * 128 + ty * 8 + 2 * i;
#pragma unroll
        for (int j = 0; j < 8; j++) {
            int n = bn * 128 + (j < 4 ? tx * 4 + j : 64 + tx * 4 + (j - 4));
            float2 v = unpack2(acc2[i][j]);
            C[m0 * N + n]       = v.x + bias[n];
            C[(m0 + 1) * N + n] = v.y + bias[n];
        }
    }
}

// ---------------- recurrent scan (R13 frozen — best measured) ----------------
__global__ __launch_bounds__(512, 1) void scan_kernel(const float* __restrict__ h0,
                                                      const float* __restrict__ Wrec,
                                                      float* __restrict__ hfinal) {
    __shared__ __align__(16) float h_s[4 * H_];   // [b][k]
    __shared__ float red[8][4][64];               // [kg][b][j]

    const int tid = threadIdx.x;
    const int bg = blockIdx.x >> 3;   // 0..15
    const int ng = blockIdx.x & 7;    // 0..7
    const int w = tid >> 5, lane = tid & 31;
    const int kg = w >> 1;                         // 0..7 -> 64-wide K slice
    const int jl = ((w & 1) << 5) | lane;          // 0..63 local output col
    const int jg = ng * 64 + jl;                   // global output col
    const int k0 = kg * 64;

    // ---- load W_rec[jg][k0..k0+63] into registers as 32 f32x2 pairs
    unsigned long long Wr[32];
    {
        const float4* wp = (const float4*)&Wrec[(size_t)jg * H_ + k0];
#pragma unroll
        for (int i = 0; i < 16; i++) {
            float4 v = wp[i];
            Wr[2 * i]     = pack2(v.x, v.y);
            Wr[2 * i + 1] = pack2(v.z, v.w);
        }
    }

    // ---- reducer identity (first 256 threads): (rb, rj)
    const int rb = tid >> 6;          // 0..3 for tid<256
    const int rj = tid & 63;
    float xr = 0.f;
    size_t xin_base = 0;
    if (tid < 256) {
        xin_base = ((size_t)(bg * 4 + rb) * S_) * H_ + (size_t)ng * 64 + rj;
        xr = g_xin[xin_base];   // xin for t=0 (gemm ran before us, stream order)
    }

    const float* hsrc0 = h0 + (size_t)bg * 4 * H_;

    for (int t = 0; t < S_; t++) {
        // ---- load h for our 4 batches into smem (2048 floats, 1 float4/thread)
        const float* hs_src = (t == 0) ? hsrc0 : &g_h[t & 1][(size_t)bg * 4 * H_];
        ((float4*)h_s)[tid] = ((const float4*)hs_src)[tid];
        __syncthreads();

        // ---- partial GEMM: acc[b] = sum over our 64-wide K slice (f32x2)
        unsigned long long acc0 = 0, acc1 = 0, acc2 = 0, acc3 = 0;
        {
            const ulonglong2* hp0 = (const ulonglong2*)&h_s[0 * H_ + k0];
            const ulonglong2* hp1 = (const ulonglong2*)&h_s[1 * H_ + k0];
            const ulonglong2* hp2 = (const ulonglong2*)&h_s[2 * H_ + k0];
            const ulonglong2* hp3 = (const ulonglong2*)&h_s[3 * H_ + k0];
#pragma unroll
            for (int i = 0; i < 16; i++) {
                ulonglong2 u0 = hp0[i];
                acc0 = ffma2(Wr[2 * i], u0.x, acc0);
                acc0 = ffma2(Wr[2 * i + 1], u0.y, acc0);
                ulonglong2 u1 = hp1[i];
                acc1 = ffma2(Wr[2 * i], u1.x, acc1);
                acc1 = ffma2(Wr[2 * i + 1], u1.y, acc1);
                ulonglong2 u2 = hp2[i];
                acc2 = ffma2(Wr[2 * i], u2.x, acc2);
                acc2 = ffma2(Wr[2 * i + 1], u2.y, acc2);
                ulonglong2 u3 = hp3[i];
                acc3 = ffma2(Wr[2 * i], u3.x, acc3);
                acc3 = ffma2(Wr[2 * i + 1], u3.y, acc3);
            }
        }
        float2 a0 = unpack2(acc0), a1 = unpack2(acc1);
        float2 a2 = unpack2(acc2), a3 = unpack2(acc3);
        red[kg][0][jl] = a0.x + a0.y;
        red[kg][1][jl] = a1.x + a1.y;
        red[kg][2][jl] = a2.x + a2.y;
        red[kg][3][jl] = a3.x + a3.y;
        __syncthreads();

        // ---- reduce over 8 K-slices, add xin, tanh.approx, publish h
        float hn = 0.f;
        int bglob = 0;
        if (tid < 256) {
            float s = xr;
#pragma unroll
            for (int q = 0; q < 8; q++) s += red[q][rb][rj];
            hn = tanh_approx(s);
            bglob = bg * 4 + rb;
            g_h[(t + 1) & 1][(size_t)bglob * H_ + ng * 64 + rj] = hn;
            if (t == S_ - 1) hfinal[(size_t)bglob * H_ + ng * 64 + rj] = hn;
            if (t + 1 < S_) xr = g_xin[xin_base + (size_t)(t + 1) * H_]; // prefetch
        }
        __syncthreads();   // all h writes issued before the elected fence

        // ---- per-batch-group barrier (8 CTAs), slice-padded counter
        if (tid == 0) {
            __threadfence();                       // publish our h slice gpu-wide
            atomicAdd(&g_bar[bg][0], 1u);
            unsigned tgt = 8u * (unsigned)(t + 1);
            while (*(volatile unsigned*)&g_bar[bg][0] < tgt) { }
            __threadfence();                       // acquire peers' h slices
        }

        // ---- history write: off the critical inter-CTA chain
        if (tid < 256)
            g_hs[((size_t)bglob * S_ + t) * H_ + ng * 64 + rj] = hn;

        __syncthreads();                           // release whole CTA
    }
}

// ---------------- launch ------------------------------------------------------
extern "C" void kernel_launch(void* const* d_in, const int* in_sizes, int n_in,
                              void* d_out, int out_size) {
    const float* inputs  = (const float*)d_in[0];
    const float* h0      = (const float*)d_in[1];
    const float* W_in_w  = (const float*)d_in[2];
    const float* W_in_b  = (const float*)d_in[3];
    const float* W_rec_w = (const float*)d_in[4];
    const float* W_out_w = (const float*)d_in[5];
    const float* W_out_b = (const float*)d_in[6];

    float* out    = (float*)d_out;                      // (B,S,O)
    float* hfinal = out + (size_t)B_ * S_ * O_;         // (B,H)

    // 1) xin = inputs @ W_in^T + b   -> g_xin          (launch #0)
    {
        dim3 grid(B_ * S_ / 128, H_ / 128);
        gemm_kernel<H_, I_, false, true><<<grid, 256>>>(inputs, W_in_w, W_in_b, nullptr);
    }
    // 2) init h double-buffer + barriers               (launch #1)
    init_kernel<<<(B_ * H_ + 255) / 256, 256>>>(h0);

    // 3) alignment dummy so ncu captures the scan      (launch #2)
    dummy_kernel<<<1, 32>>>();

    // 4) sequential scan                               (launch #3 <- ncu capture)
    scan_kernel<<<128, 512>>>(h0, W_rec_w, hfinal);

    // 5) outputs = hs @ W_out^T + b  -> d_out          (launch #4)
    {
        dim3 grid(B_ * S_ / 128, O_ / 128);
        gemm_kernel<O_, H_, true, false><<<grid, 256>>>(nullptr, W_out_w, W_out_b, out);
    }
}